// round 15
// baseline (speedup 1.0000x reference)
#include <cuda_runtime.h>
#include <cuda_bf16.h>
#include <cstdint>

#define S_LEN 32768
#define HDIM  1024
#define H3    3072
#define BM    128                 // s-rows per unit
#define BN    128                 // i-cols per unit (one pass)
#define NPASS 8
#define KCH   64                  // k elements per chunk (128 B bf16 row)
#define CH_PER_UNIT 16
#define NTILES (S_LEN / BM)       // 256
#define NUNITS (NTILES * NPASS)   // 2048
#define GRID_MAIN 296             // 2 CTAs x 148 SMs, persistent
#define NTHR  128
#define NSTAGE 3

// SMEM (bytes). Rows exactly 128 B, XOR-swizzled (SW128).
#define STG    16384              // 128 rows * 128 B
#define SM_A   0                  // 3 stages
#define SM_B   (NSTAGE * STG)                // 49152, 3 stages
#define SM_RED (SM_B + NSTAGE * STG)         // 98304 (256 floats)
#define SMEM_TOTAL (SM_RED + 1024 + 16)      // 99344 (x2 CTA/SM = 199 KB)

__device__ float g_c[HDIM];
__device__ float g_lp[NPASS * S_LEN];        // per-pass logit partials (1 MB)
__device__ float g_part[S_LEN / 256];        // 128 exp block sums
__device__ __align__(16) __nv_bfloat16 g_encb[(size_t)S_LEN * HDIM]; // 64 MB
__device__ __align__(16) __nv_bfloat16 g_wb[HDIM * HDIM];            // 2 MB

// ---------------- helpers ----------------
__device__ __forceinline__ unsigned smem_u32(const void* p) {
    return (unsigned)__cvta_generic_to_shared(p);
}
__device__ __forceinline__ float fast_tanh(float x) {
    float e, r;
    asm("ex2.approx.f32 %0, %1;" : "=f"(e) : "f"(x * 2.885390082f));
    asm("rcp.approx.f32 %0, %1;" : "=f"(r) : "f"(e + 1.0f));
    return fmaf(-2.0f, r, 1.0f);
}
__device__ __forceinline__ void mma16(float* d, const uint32_t* a,
                                      uint32_t b0, uint32_t b1) {
    asm volatile(
        "mma.sync.aligned.m16n8k16.row.col.f32.bf16.bf16.f32 "
        "{%0,%1,%2,%3}, {%4,%5,%6,%7}, {%8,%9}, {%0,%1,%2,%3};"
        : "+f"(d[0]), "+f"(d[1]), "+f"(d[2]), "+f"(d[3])
        : "r"(a[0]), "r"(a[1]), "r"(a[2]), "r"(a[3]), "r"(b0), "r"(b1));
}
__device__ __forceinline__ void ldsm4(uint32_t* d, unsigned addr) {
    asm volatile(
        "ldmatrix.sync.aligned.m8n8.x4.shared.b16 {%0,%1,%2,%3}, [%4];"
        : "=r"(d[0]), "=r"(d[1]), "=r"(d[2]), "=r"(d[3]) : "r"(addr));
}

// cp.async one chunk: A 128x64 bf16 (rows s0..), B 128x64 bf16 (rows i0..)
__device__ __forceinline__ void load_chunk(unsigned sb, int stage, int ch,
                                           int s0, int i0, int tid) {
    const int kt = ch * KCH;
    const unsigned ab = sb + SM_A + stage * STG;
    const unsigned bb = sb + SM_B + stage * STG;
    #pragma unroll
    for (int j = 0; j < 8; j++) {              // A: 1024 x 16B
        int idx = tid + j * NTHR;
        int row = idx >> 3, q = idx & 7;
        unsigned dst = ab + (unsigned)(row * 128 + ((q ^ (row & 7)) * 16));
        const __nv_bfloat16* src = g_encb + (size_t)(s0 + row) * HDIM + kt + q * 8;
        asm volatile("cp.async.cg.shared.global [%0], [%1], 16;"
                     :: "r"(dst), "l"(src) : "memory");
    }
    #pragma unroll
    for (int j = 0; j < 8; j++) {              // B: 1024 x 16B
        int idx = tid + j * NTHR;
        int row = idx >> 3, q = idx & 7;
        unsigned dst = bb + (unsigned)(row * 128 + ((q ^ (row & 7)) * 16));
        const __nv_bfloat16* src = g_wb + (size_t)(i0 + row) * HDIM + kt + q * 8;
        asm volatile("cp.async.cg.shared.global [%0], [%1], 16;"
                     :: "r"(dst), "l"(src) : "memory");
    }
    asm volatile("cp.async.commit_group;" ::: "memory");
}

// ---------------------------------------------------------------------------
// Kernel A: enc fp32 -> bf16 (RTN), 16 floats per thread, grid 8192
// ---------------------------------------------------------------------------
__global__ void convert_enc_kernel(const float* __restrict__ enc) {
    size_t gid = (size_t)blockIdx.x * blockDim.x + threadIdx.x;
    size_t base = gid * 16;
    float4 a0 = *(const float4*)(enc + base);
    float4 a1 = *(const float4*)(enc + base + 4);
    float4 a2 = *(const float4*)(enc + base + 8);
    float4 a3 = *(const float4*)(enc + base + 12);
    __nv_bfloat162 r[8];
    r[0] = __floats2bfloat162_rn(a0.x, a0.y);
    r[1] = __floats2bfloat162_rn(a0.z, a0.w);
    r[2] = __floats2bfloat162_rn(a1.x, a1.y);
    r[3] = __floats2bfloat162_rn(a1.z, a1.w);
    r[4] = __floats2bfloat162_rn(a2.x, a2.y);
    r[5] = __floats2bfloat162_rn(a2.z, a2.w);
    r[6] = __floats2bfloat162_rn(a3.x, a3.y);
    r[7] = __floats2bfloat162_rn(a3.z, a3.w);
    *(uint4*)(g_encb + base)     = *(uint4*)&r[0];
    *(uint4*)(g_encb + base + 8) = *(uint4*)&r[4];
}

// ---------------------------------------------------------------------------
// Kernel B (fused): blocks 0..511 convert W2 rows to bf16;
//                   blocks 512..639 compute c[i] (one warp per i).
// ---------------------------------------------------------------------------
__global__ void prep_kernel(const float* __restrict__ attn_w,
                            const float* __restrict__ hidden,
                            const float* __restrict__ attn_b) {
    if (blockIdx.x < 512) {
        size_t gid = (size_t)blockIdx.x * 256 + threadIdx.x;
        size_t base = gid * 8;
        size_t i = base >> 10, k = base & 1023;
        const float* src = attn_w + i * H3 + 2 * HDIM + k;
        float4 a = *(const float4*)src;
        float4 b = *(const float4*)(src + 4);
        __nv_bfloat162 r[4];
        r[0] = __floats2bfloat162_rn(a.x, a.y);
        r[1] = __floats2bfloat162_rn(a.z, a.w);
        r[2] = __floats2bfloat162_rn(b.x, b.y);
        r[3] = __floats2bfloat162_rn(b.z, b.w);
        *(uint4*)(g_wb + base) = *(uint4*)r;
    } else {
        int warp = ((blockIdx.x - 512) * 256 + threadIdx.x) >> 5;  // 0..1023
        int lane = threadIdx.x & 31;
        const float* wrow = attn_w + (size_t)warp * H3;
        float s = 0.f;
        #pragma unroll 8
        for (int j = lane; j < 2 * HDIM; j += 32)
            s += hidden[j] * wrow[j];
        #pragma unroll
        for (int off = 16; off; off >>= 1)
            s += __shfl_down_sync(0xffffffffu, s, off);
        if (lane == 0) g_c[warp] = s + attn_b[warp];
    }
}

// ---------------------------------------------------------------------------
// Kernel 2: persistent bf16 m16n8k16 GEMM, cross-unit continuous 3-stage ring.
//   4 warps = 2(M) x 2(N).  Warp tile 64x64 (mt=4, nt=8).  acc = 128 regs.
//   One pipeline drain per CTA (not per unit).
// ---------------------------------------------------------------------------
__global__ __launch_bounds__(NTHR, 2)
void attn_main_kernel(const float* __restrict__ v_w) {
    extern __shared__ char smem[];
    const unsigned sb = smem_u32(smem);
    const int tid  = threadIdx.x;
    const int wid  = tid >> 5;
    const int lane = tid & 31;
    const int g    = lane >> 2;        // 0..7
    const int c    = lane & 3;         // 0..3
    const int m0   = (wid & 1) * 64;   // 2 M-warps
    const int n0   = (wid >> 1) * 64;  // 2 N-warps
    const int ub   = blockIdx.x;

    float* red = (float*)(smem + SM_RED);

    // number of units for this CTA and total chunk stream length
    const int nu = (NUNITS - 1 - ub) / GRID_MAIN + 1;   // 6 or 7
    const int nc = nu * CH_PER_UNIT;

    // ldmatrix lane geometry (rows fixed per lane; 16B column unit swizzled)
    const int arow  = m0 + ((lane >> 3) & 1) * 8 + (lane & 7); // + mt*16
    const int aswz  = arow & 7;
    const int acol  = lane >> 4;                               // 0..1 (k half)
    const int brow  = n0 + (lane >> 4) * 8 + (lane & 7);       // + p*16
    const int bswz  = brow & 7;
    const int bcol  = (lane >> 3) & 1;                         // 0..1 (k half)

    // prologue: chunks 0, 1 of the stream (both in unit 0 of this CTA)
    {
        const int u0 = ub;
        const int s0 = (u0 >> 3) * BM, i0 = (u0 & 7) * BN;
        load_chunk(sb, 0, 0, s0, i0, tid);
        load_chunk(sb, 1, 1, s0, i0, tid);
    }

    float acc[4][8][4];

    for (int cc = 0; cc < nc; cc++) {
        const int ch    = cc & (CH_PER_UNIT - 1);
        const int u     = ub + (cc >> 4) * GRID_MAIN;
        const int stage = cc % NSTAGE;

        if (cc < nc - 1)
            asm volatile("cp.async.wait_group 1;" ::: "memory");
        else
            asm volatile("cp.async.wait_group 0;" ::: "memory");
        __syncthreads();

        // refill the stage freed at cc-1 with stream chunk cc+2 (any unit)
        if (cc + 2 < nc) {
            const int cc2 = cc + 2;
            const int u2  = ub + (cc2 >> 4) * GRID_MAIN;
            load_chunk(sb, cc2 % NSTAGE, cc2 & (CH_PER_UNIT - 1),
                       (u2 >> 3) * BM, (u2 & 7) * BN, tid);
        }

        if (ch == 0) {
            #pragma unroll
            for (int mt = 0; mt < 4; mt++)
                #pragma unroll
                for (int nt = 0; nt < 8; nt++)
                    #pragma unroll
                    for (int q = 0; q < 4; q++) acc[mt][nt][q] = 0.f;
        }

        const unsigned aS = sb + SM_A + stage * STG;
        const unsigned bS = sb + SM_B + stage * STG;

        #pragma unroll
        for (int ks = 0; ks < 4; ks++) {       // four k16 steps cover KCH=64
            uint32_t af[4][4], bf[4][4];
            const int aq = ((ks * 2 + acol) ^ aswz) * 16;
            const int bq = ((ks * 2 + bcol) ^ bswz) * 16;
            #pragma unroll
            for (int mt = 0; mt < 4; mt++)
                ldsm4(af[mt], aS + (unsigned)((arow + mt * 16) * 128 + aq));
            #pragma unroll
            for (int p = 0; p < 4; p++)
                ldsm4(bf[p], bS + (unsigned)((brow + p * 16) * 128 + bq));
            #pragma unroll
            for (int p = 0; p < 4; p++) {
                #pragma unroll
                for (int mt = 0; mt < 4; mt++) {
                    mma16(acc[mt][2 * p + 0], af[mt], bf[p][0], bf[p][1]);
                    mma16(acc[mt][2 * p + 1], af[mt], bf[p][2], bf[p][3]);
                }
            }
        }

        // unit epilogue at last chunk of each unit
        if (ch == CH_PER_UNIT - 1) {
            const int s0 = (u >> 3) * BM;
            const int i0 = (u & 7) * BN;
            float part[8];
            #pragma unroll
            for (int r = 0; r < 8; r++) part[r] = 0.f;
            #pragma unroll
            for (int mt = 0; mt < 4; mt++) {
                #pragma unroll
                for (int nt = 0; nt < 8; nt++) {
                    int i = i0 + n0 + nt * 8 + c * 2;
                    float2 cv = __ldg((const float2*)(g_c + i));
                    float2 vv = __ldg((const float2*)(v_w + i));
                    part[mt*2+0] = fmaf(vv.x, fast_tanh(acc[mt][nt][0] + cv.x),
                                   fmaf(vv.y, fast_tanh(acc[mt][nt][1] + cv.y),
                                        part[mt*2+0]));
                    part[mt*2+1] = fmaf(vv.x, fast_tanh(acc[mt][nt][2] + cv.x),
                                   fmaf(vv.y, fast_tanh(acc[mt][nt][3] + cv.y),
                                        part[mt*2+1]));
                }
            }
            #pragma unroll
            for (int r = 0; r < 8; r++) {
                part[r] += __shfl_xor_sync(0xffffffffu, part[r], 1);
                part[r] += __shfl_xor_sync(0xffffffffu, part[r], 2);
            }
            if (c == 0) {
                const int nw = wid >> 1;
                #pragma unroll
                for (int mt = 0; mt < 4; mt++) {
                    #pragma unroll
                    for (int h = 0; h < 2; h++) {
                        int row = m0 + mt * 16 + h * 8 + g;
                        red[nw * 128 + row] = part[mt * 2 + h];
                    }
                }
            }
            __syncthreads();
            g_lp[(u & 7) * S_LEN + s0 + tid] = red[tid] + red[128 + tid];
        }
    }
}

// ---------------------------------------------------------------------------
// Kernel 3: logits = sum of 8 pass partials (fixed order), exp, block sums.
// ---------------------------------------------------------------------------
__global__ void exp_kernel(float* __restrict__ out) {
    __shared__ float sr[8];
    int s = blockIdx.x * 256 + threadIdx.x;
    float logit = 0.f;
    #pragma unroll
    for (int p = 0; p < NPASS; p++)
        logit += g_lp[p * S_LEN + s];
    float ex = expf(logit);                    // |logit| <= ~26, unshifted safe
    out[s] = ex;
    float w = ex;
    #pragma unroll
    for (int off = 16; off; off >>= 1)
        w += __shfl_down_sync(0xffffffffu, w, off);
    if ((threadIdx.x & 31) == 0) sr[threadIdx.x >> 5] = w;
    __syncthreads();
    if (threadIdx.x == 0) {
        float t = 0.f;
        #pragma unroll
        for (int y = 0; y < 8; y++) t += sr[y];
        g_part[blockIdx.x] = t;
    }
}

// ---------------------------------------------------------------------------
// Kernel 4: finalize — redundant deterministic reduce of 128 partials, scale.
// ---------------------------------------------------------------------------
__global__ void finalize_kernel(float* __restrict__ out) {
    __shared__ float sm[128];
    int t = threadIdx.x;
    if (t < 128) sm[t] = g_part[t];
    __syncthreads();
    #pragma unroll
    for (int o = 64; o > 0; o >>= 1) {
        if (t < o) sm[t] += sm[t + o];
        __syncthreads();
    }
    float inv = 1.f / sm[0];
    int i = blockIdx.x * 256 + t;
    out[i] *= inv;
}

// ---------------------------------------------------------------------------
extern "C" void kernel_launch(void* const* d_in, const int* in_sizes, int n_in,
                              void* d_out, int out_size) {
    const float* hidden = (const float*)d_in[0];
    const float* enc    = (const float*)d_in[1];
    const float* attn_w = (const float*)d_in[2];
    const float* attn_b = (const float*)d_in[3];
    const float* v_w    = (const float*)d_in[4];
    float* out = (float*)d_out;

    cudaFuncSetAttribute(attn_main_kernel,
                         cudaFuncAttributeMaxDynamicSharedMemorySize, SMEM_TOTAL);

    convert_enc_kernel<<<8192, 256>>>(enc);
    prep_kernel<<<640, 256>>>(attn_w, hidden, attn_b);
    attn_main_kernel<<<GRID_MAIN, NTHR, SMEM_TOTAL>>>(v_w);
    exp_kernel<<<S_LEN / 256, 256>>>(out);
    finalize_kernel<<<S_LEN / 256, 256>>>(out);
}

// round 16
// speedup vs baseline: 1.0168x; 1.0168x over previous
#include <cuda_runtime.h>
#include <cuda_bf16.h>
#include <cstdint>

#define S_LEN 32768
#define HDIM  1024
#define H3    3072
#define BM    128                 // s-rows per unit
#define BN    128                 // i-cols per unit (one pass)
#define NPASS 8
#define KCH   64                  // k elements per chunk (128 B bf16 row)
#define CH_PER_UNIT (HDIM / KCH)  // 16
#define NTILES (S_LEN / BM)       // 256
#define NUNITS (NTILES * NPASS)   // 2048
#define GRID_MAIN 296             // 2 CTAs x 148 SMs, persistent
#define NTHR  128
#define NSTAGE 3

// SMEM (bytes). Rows exactly 128 B, XOR-swizzled (SW128).
#define STG    16384              // 128 rows * 128 B
#define SM_A   0                  // 3 stages
#define SM_B   (NSTAGE * STG)                // 49152, 3 stages
#define SM_RED (SM_B + NSTAGE * STG)         // 98304 (256 floats)
#define SMEM_TOTAL (SM_RED + 1024 + 16)      // 99344 (x2 CTA/SM = 199 KB)

__device__ float g_c[HDIM];
__device__ float g_lp[NPASS * S_LEN];        // per-pass logit partials (1 MB)
__device__ float g_part[S_LEN / 256];        // 128 exp block sums
__device__ __align__(16) __nv_bfloat16 g_encb[(size_t)S_LEN * HDIM]; // 64 MB
__device__ __align__(16) __nv_bfloat16 g_wb[HDIM * HDIM];            // 2 MB

// ---------------- helpers ----------------
__device__ __forceinline__ unsigned smem_u32(const void* p) {
    return (unsigned)__cvta_generic_to_shared(p);
}
__device__ __forceinline__ float fast_tanh(float x) {
    float e, r;
    asm("ex2.approx.f32 %0, %1;" : "=f"(e) : "f"(x * 2.885390082f));
    asm("rcp.approx.f32 %0, %1;" : "=f"(r) : "f"(e + 1.0f));
    return fmaf(-2.0f, r, 1.0f);
}
__device__ __forceinline__ void mma16(float* d, const uint32_t* a,
                                      uint32_t b0, uint32_t b1) {
    asm volatile(
        "mma.sync.aligned.m16n8k16.row.col.f32.bf16.bf16.f32 "
        "{%0,%1,%2,%3}, {%4,%5,%6,%7}, {%8,%9}, {%0,%1,%2,%3};"
        : "+f"(d[0]), "+f"(d[1]), "+f"(d[2]), "+f"(d[3])
        : "r"(a[0]), "r"(a[1]), "r"(a[2]), "r"(a[3]), "r"(b0), "r"(b1));
}
__device__ __forceinline__ void ldsm4(uint32_t* d, unsigned addr) {
    asm volatile(
        "ldmatrix.sync.aligned.m8n8.x4.shared.b16 {%0,%1,%2,%3}, [%4];"
        : "=r"(d[0]), "=r"(d[1]), "=r"(d[2]), "=r"(d[3]) : "r"(addr));
}

// cp.async one chunk of a unit: A 128x64 bf16, B 128x64 bf16 (SW128 swizzle)
__device__ __forceinline__ void load_chunk(unsigned sb, int stage, int ch,
                                           int s0, int i0, int tid) {
    const int kt = ch * KCH;
    const unsigned ab = sb + SM_A + stage * STG;
    const unsigned bb = sb + SM_B + stage * STG;
    #pragma unroll
    for (int j = 0; j < 8; j++) {              // A: 1024 x 16B
        int idx = tid + j * NTHR;
        int row = idx >> 3, q = idx & 7;
        unsigned dst = ab + (unsigned)(row * 128 + ((q ^ (row & 7)) * 16));
        const __nv_bfloat16* src = g_encb + (size_t)(s0 + row) * HDIM + kt + q * 8;
        asm volatile("cp.async.cg.shared.global [%0], [%1], 16;"
                     :: "r"(dst), "l"(src) : "memory");
    }
    #pragma unroll
    for (int j = 0; j < 8; j++) {              // B: 1024 x 16B
        int idx = tid + j * NTHR;
        int row = idx >> 3, q = idx & 7;
        unsigned dst = bb + (unsigned)(row * 128 + ((q ^ (row & 7)) * 16));
        const __nv_bfloat16* src = g_wb + (size_t)(i0 + row) * HDIM + kt + q * 8;
        asm volatile("cp.async.cg.shared.global [%0], [%1], 16;"
                     :: "r"(dst), "l"(src) : "memory");
    }
    asm volatile("cp.async.commit_group;" ::: "memory");
}

// ---------------------------------------------------------------------------
// Kernel A: enc fp32 -> bf16 (RTN), 16 floats per thread, grid 8192
// ---------------------------------------------------------------------------
__global__ void convert_enc_kernel(const float* __restrict__ enc) {
    size_t gid = (size_t)blockIdx.x * blockDim.x + threadIdx.x;
    size_t base = gid * 16;
    float4 a0 = *(const float4*)(enc + base);
    float4 a1 = *(const float4*)(enc + base + 4);
    float4 a2 = *(const float4*)(enc + base + 8);
    float4 a3 = *(const float4*)(enc + base + 12);
    __nv_bfloat162 r[8];
    r[0] = __floats2bfloat162_rn(a0.x, a0.y);
    r[1] = __floats2bfloat162_rn(a0.z, a0.w);
    r[2] = __floats2bfloat162_rn(a1.x, a1.y);
    r[3] = __floats2bfloat162_rn(a1.z, a1.w);
    r[4] = __floats2bfloat162_rn(a2.x, a2.y);
    r[5] = __floats2bfloat162_rn(a2.z, a2.w);
    r[6] = __floats2bfloat162_rn(a3.x, a3.y);
    r[7] = __floats2bfloat162_rn(a3.z, a3.w);
    *(uint4*)(g_encb + base)     = *(uint4*)&r[0];
    *(uint4*)(g_encb + base + 8) = *(uint4*)&r[4];
}

// ---------------------------------------------------------------------------
// Kernel B (fused): blocks 0..511 convert W2 rows to bf16;
//                   blocks 512..639 compute c[i] (one warp per i).
// ---------------------------------------------------------------------------
__global__ void prep_kernel(const float* __restrict__ attn_w,
                            const float* __restrict__ hidden,
                            const float* __restrict__ attn_b) {
    if (blockIdx.x < 512) {
        size_t gid = (size_t)blockIdx.x * 256 + threadIdx.x;
        size_t base = gid * 8;
        size_t i = base >> 10, k = base & 1023;
        const float* src = attn_w + i * H3 + 2 * HDIM + k;
        float4 a = *(const float4*)src;
        float4 b = *(const float4*)(src + 4);
        __nv_bfloat162 r[4];
        r[0] = __floats2bfloat162_rn(a.x, a.y);
        r[1] = __floats2bfloat162_rn(a.z, a.w);
        r[2] = __floats2bfloat162_rn(b.x, b.y);
        r[3] = __floats2bfloat162_rn(b.z, b.w);
        *(uint4*)(g_wb + base) = *(uint4*)r;
    } else {
        int warp = ((blockIdx.x - 512) * 256 + threadIdx.x) >> 5;  // 0..1023
        int lane = threadIdx.x & 31;
        const float* wrow = attn_w + (size_t)warp * H3;
        float s = 0.f;
        #pragma unroll 8
        for (int j = lane; j < 2 * HDIM; j += 32)
            s += hidden[j] * wrow[j];
        #pragma unroll
        for (int off = 16; off; off >>= 1)
            s += __shfl_down_sync(0xffffffffu, s, off);
        if (lane == 0) g_c[warp] = s + attn_b[warp];
    }
}

// ---------------------------------------------------------------------------
// Kernel 2: persistent bf16 m16n8k16 GEMM over 2048 (tile, pass) units.
//   4 warps = 2(M) x 2(N).  Warp tile 64x64 (mt=4, nt=8).  acc = 128 regs.
//   Unit: 16 k-chunks + fused tanh/v-dot epilogue -> g_lp[pass][s].
//   (R14 proven version — per-unit prologue, per-unit 3-stage ring.)
// ---------------------------------------------------------------------------
__global__ __launch_bounds__(NTHR, 2)
void attn_main_kernel(const float* __restrict__ v_w) {
    extern __shared__ char smem[];
    const unsigned sb = smem_u32(smem);
    const int tid  = threadIdx.x;
    const int wid  = tid >> 5;
    const int lane = tid & 31;
    const int g    = lane >> 2;        // 0..7
    const int c    = lane & 3;         // 0..3
    const int m0   = (wid & 1) * 64;   // 2 M-warps
    const int n0   = (wid >> 1) * 64;  // 2 N-warps

    float* red = (float*)(smem + SM_RED);

    // ldmatrix lane geometry (rows fixed per lane; 16B column unit swizzled)
    const int arow  = m0 + ((lane >> 3) & 1) * 8 + (lane & 7); // + mt*16
    const int aswz  = arow & 7;
    const int acol  = lane >> 4;                               // 0..1 (k half)
    const int brow  = n0 + (lane >> 4) * 8 + (lane & 7);       // + p*16
    const int bswz  = brow & 7;
    const int bcol  = (lane >> 3) & 1;                         // 0..1 (k half)

    for (int u = blockIdx.x; u < NUNITS; u += GRID_MAIN) {
        const int tile = u >> 3;
        const int pass = u & 7;
        const int s0   = tile * BM;
        const int i0   = pass * BN;

        // unit prologue: chunks 0, 1 into stages 0, 1
        load_chunk(sb, 0, 0, s0, i0, tid);
        load_chunk(sb, 1, 1, s0, i0, tid);

        float acc[4][8][4];
        #pragma unroll
        for (int mt = 0; mt < 4; mt++)
            #pragma unroll
            for (int nt = 0; nt < 8; nt++)
                #pragma unroll
                for (int q = 0; q < 4; q++) acc[mt][nt][q] = 0.f;

        for (int ch = 0; ch < CH_PER_UNIT; ch++) {
            const int stage = ch % NSTAGE;
            if (ch < CH_PER_UNIT - 1)
                asm volatile("cp.async.wait_group 1;" ::: "memory");
            else
                asm volatile("cp.async.wait_group 0;" ::: "memory");
            __syncthreads();

            if (ch + 2 < CH_PER_UNIT)
                load_chunk(sb, (ch + 2) % NSTAGE, ch + 2, s0, i0, tid);

            const unsigned aS = sb + SM_A + stage * STG;
            const unsigned bS = sb + SM_B + stage * STG;

            #pragma unroll
            for (int ks = 0; ks < 4; ks++) {   // four k16 steps cover KCH=64
                uint32_t af[4][4], bf[4][4];
                const int aq = ((ks * 2 + acol) ^ aswz) * 16;
                const int bq = ((ks * 2 + bcol) ^ bswz) * 16;
                #pragma unroll
                for (int mt = 0; mt < 4; mt++)
                    ldsm4(af[mt], aS + (unsigned)((arow + mt * 16) * 128 + aq));
                #pragma unroll
                for (int p = 0; p < 4; p++)
                    ldsm4(bf[p], bS + (unsigned)((brow + p * 16) * 128 + bq));
                #pragma unroll
                for (int p = 0; p < 4; p++) {
                    #pragma unroll
                    for (int mt = 0; mt < 4; mt++) {
                        mma16(acc[mt][2 * p + 0], af[mt], bf[p][0], bf[p][1]);
                        mma16(acc[mt][2 * p + 1], af[mt], bf[p][2], bf[p][3]);
                    }
                }
            }
        }

        // unit epilogue: tanh + v-dot -> per-thread partials
        float part[8];
        #pragma unroll
        for (int r = 0; r < 8; r++) part[r] = 0.f;
        #pragma unroll
        for (int mt = 0; mt < 4; mt++) {
            #pragma unroll
            for (int nt = 0; nt < 8; nt++) {
                int i = i0 + n0 + nt * 8 + c * 2;
                float2 cv = __ldg((const float2*)(g_c + i));
                float2 vv = __ldg((const float2*)(v_w + i));
                part[mt*2+0] = fmaf(vv.x, fast_tanh(acc[mt][nt][0] + cv.x),
                               fmaf(vv.y, fast_tanh(acc[mt][nt][1] + cv.y),
                                    part[mt*2+0]));
                part[mt*2+1] = fmaf(vv.x, fast_tanh(acc[mt][nt][2] + cv.x),
                               fmaf(vv.y, fast_tanh(acc[mt][nt][3] + cv.y),
                                    part[mt*2+1]));
            }
        }
        #pragma unroll
        for (int r = 0; r < 8; r++) {
            part[r] += __shfl_xor_sync(0xffffffffu, part[r], 1);
            part[r] += __shfl_xor_sync(0xffffffffu, part[r], 2);
        }
        if (c == 0) {
            const int nw = wid >> 1;
            #pragma unroll
            for (int mt = 0; mt < 4; mt++) {
                #pragma unroll
                for (int h = 0; h < 2; h++) {
                    int row = m0 + mt * 16 + h * 8 + g;
                    red[nw * 128 + row] = part[mt * 2 + h];
                }
            }
        }
        __syncthreads();                       // also fences stage reuse
        g_lp[pass * S_LEN + s0 + tid] = red[tid] + red[128 + tid];
    }
}

// ---------------------------------------------------------------------------
// Kernel 3: logits = sum of 8 pass partials (fixed order), exp, block sums.
// ---------------------------------------------------------------------------
__global__ void exp_kernel(float* __restrict__ out) {
    __shared__ float sr[8];
    int s = blockIdx.x * 256 + threadIdx.x;
    float logit = 0.f;
    #pragma unroll
    for (int p = 0; p < NPASS; p++)
        logit += g_lp[p * S_LEN + s];
    float ex = expf(logit);                    // |logit| <= ~26, unshifted safe
    out[s] = ex;
    float w = ex;
    #pragma unroll
    for (int off = 16; off; off >>= 1)
        w += __shfl_down_sync(0xffffffffu, w, off);
    if ((threadIdx.x & 31) == 0) sr[threadIdx.x >> 5] = w;
    __syncthreads();
    if (threadIdx.x == 0) {
        float t = 0.f;
        #pragma unroll
        for (int y = 0; y < 8; y++) t += sr[y];
        g_part[blockIdx.x] = t;
    }
}

// ---------------------------------------------------------------------------
// Kernel 4: finalize — redundant deterministic reduce of 128 partials, scale.
// ---------------------------------------------------------------------------
__global__ void finalize_kernel(float* __restrict__ out) {
    __shared__ float sm[128];
    int t = threadIdx.x;
    if (t < 128) sm[t] = g_part[t];
    __syncthreads();
    #pragma unroll
    for (int o = 64; o > 0; o >>= 1) {
        if (t < o) sm[t] += sm[t + o];
        __syncthreads();
    }
    float inv = 1.f / sm[0];
    int i = blockIdx.x * 256 + t;
    out[i] *= inv;
}

// ---------------------------------------------------------------------------
extern "C" void kernel_launch(void* const* d_in, const int* in_sizes, int n_in,
                              void* d_out, int out_size) {
    const float* hidden = (const float*)d_in[0];
    const float* enc    = (const float*)d_in[1];
    const float* attn_w = (const float*)d_in[2];
    const float* attn_b = (const float*)d_in[3];
    const float* v_w    = (const float*)d_in[4];
    float* out = (float*)d_out;

    cudaFuncSetAttribute(attn_main_kernel,
                         cudaFuncAttributeMaxDynamicSharedMemorySize, SMEM_TOTAL);

    convert_enc_kernel<<<8192, 256>>>(enc);
    prep_kernel<<<640, 256>>>(attn_w, hidden, attn_b);
    attn_main_kernel<<<GRID_MAIN, NTHR, SMEM_TOTAL>>>(v_w);
    exp_kernel<<<S_LEN / 256, 256>>>(out);
    finalize_kernel<<<S_LEN / 256, 256>>>(out);
}

// round 17
// speedup vs baseline: 1.0324x; 1.0154x over previous
#include <cuda_runtime.h>
#include <cuda_bf16.h>
#include <cstdint>

#define S_LEN 32768
#define HDIM  1024
#define H3    3072
#define BM    128                 // s-rows per unit
#define BN    128                 // i-cols per unit (one pass)
#define NPASS 8
#define KCH   64                  // k elements per chunk (128 B bf16 row)
#define CH_PER_UNIT (HDIM / KCH)  // 16
#define NTILES (S_LEN / BM)       // 256
#define NUNITS (NTILES * NPASS)   // 2048
#define GRID_MAIN 296             // 2 CTAs x 148 SMs, persistent
#define NTHR  128
#define NSTAGE 3
#define NBLK_TAIL 128             // exp+finalize blocks (co-resident)

// SMEM (bytes). Rows exactly 128 B, XOR-swizzled (SW128).
#define STG    16384              // 128 rows * 128 B
#define SM_A   0                  // 3 stages
#define SM_B   (NSTAGE * STG)                // 49152, 3 stages
#define SM_RED (SM_B + NSTAGE * STG)         // 98304 (256 floats)
#define SMEM_TOTAL (SM_RED + 1024 + 16)      // 99344 (x2 CTA/SM = 199 KB)

__device__ float g_c[HDIM];
__device__ float g_lp[NPASS * S_LEN];        // per-pass logit partials (1 MB)
__device__ float g_part[NBLK_TAIL];          // 128 exp block sums
__device__ unsigned long long g_tick;        // monotone ticket counter
__device__ __align__(16) __nv_bfloat16 g_encb[(size_t)S_LEN * HDIM]; // 64 MB
__device__ __align__(16) __nv_bfloat16 g_wb[HDIM * HDIM];            // 2 MB

// ---------------- helpers ----------------
__device__ __forceinline__ unsigned smem_u32(const void* p) {
    return (unsigned)__cvta_generic_to_shared(p);
}
__device__ __forceinline__ float fast_tanh(float x) {
    float e, r;
    asm("ex2.approx.f32 %0, %1;" : "=f"(e) : "f"(x * 2.885390082f));
    asm("rcp.approx.f32 %0, %1;" : "=f"(r) : "f"(e + 1.0f));
    return fmaf(-2.0f, r, 1.0f);
}
__device__ __forceinline__ void mma16(float* d, const uint32_t* a,
                                      uint32_t b0, uint32_t b1) {
    asm volatile(
        "mma.sync.aligned.m16n8k16.row.col.f32.bf16.bf16.f32 "
        "{%0,%1,%2,%3}, {%4,%5,%6,%7}, {%8,%9}, {%0,%1,%2,%3};"
        : "+f"(d[0]), "+f"(d[1]), "+f"(d[2]), "+f"(d[3])
        : "r"(a[0]), "r"(a[1]), "r"(a[2]), "r"(a[3]), "r"(b0), "r"(b1));
}
__device__ __forceinline__ void ldsm4(uint32_t* d, unsigned addr) {
    asm volatile(
        "ldmatrix.sync.aligned.m8n8.x4.shared.b16 {%0,%1,%2,%3}, [%4];"
        : "=r"(d[0]), "=r"(d[1]), "=r"(d[2]), "=r"(d[3]) : "r"(addr));
}

// cp.async one chunk of a unit: A 128x64 bf16, B 128x64 bf16 (SW128 swizzle)
__device__ __forceinline__ void load_chunk(unsigned sb, int stage, int ch,
                                           int s0, int i0, int tid) {
    const int kt = ch * KCH;
    const unsigned ab = sb + SM_A + stage * STG;
    const unsigned bb = sb + SM_B + stage * STG;
    #pragma unroll
    for (int j = 0; j < 8; j++) {              // A: 1024 x 16B
        int idx = tid + j * NTHR;
        int row = idx >> 3, q = idx & 7;
        unsigned dst = ab + (unsigned)(row * 128 + ((q ^ (row & 7)) * 16));
        const __nv_bfloat16* src = g_encb + (size_t)(s0 + row) * HDIM + kt + q * 8;
        asm volatile("cp.async.cg.shared.global [%0], [%1], 16;"
                     :: "r"(dst), "l"(src) : "memory");
    }
    #pragma unroll
    for (int j = 0; j < 8; j++) {              // B: 1024 x 16B
        int idx = tid + j * NTHR;
        int row = idx >> 3, q = idx & 7;
        unsigned dst = bb + (unsigned)(row * 128 + ((q ^ (row & 7)) * 16));
        const __nv_bfloat16* src = g_wb + (size_t)(i0 + row) * HDIM + kt + q * 8;
        asm volatile("cp.async.cg.shared.global [%0], [%1], 16;"
                     :: "r"(dst), "l"(src) : "memory");
    }
    asm volatile("cp.async.commit_group;" ::: "memory");
}

// ---------------------------------------------------------------------------
// Kernel 1 (fused prep): blocks 0..8191   convert enc -> bf16 (16 f/thread)
//                        blocks 8192..8703 convert W2 -> bf16
//                        blocks 8704..8831 compute c[i] (one warp per i)
// ---------------------------------------------------------------------------
__global__ void prep_all_kernel(const float* __restrict__ enc,
                                const float* __restrict__ attn_w,
                                const float* __restrict__ hidden,
                                const float* __restrict__ attn_b) {
    if (blockIdx.x < 8192) {
        size_t gid = (size_t)blockIdx.x * 256 + threadIdx.x;
        size_t base = gid * 16;
        float4 a0 = *(const float4*)(enc + base);
        float4 a1 = *(const float4*)(enc + base + 4);
        float4 a2 = *(const float4*)(enc + base + 8);
        float4 a3 = *(const float4*)(enc + base + 12);
        __nv_bfloat162 r[8];
        r[0] = __floats2bfloat162_rn(a0.x, a0.y);
        r[1] = __floats2bfloat162_rn(a0.z, a0.w);
        r[2] = __floats2bfloat162_rn(a1.x, a1.y);
        r[3] = __floats2bfloat162_rn(a1.z, a1.w);
        r[4] = __floats2bfloat162_rn(a2.x, a2.y);
        r[5] = __floats2bfloat162_rn(a2.z, a2.w);
        r[6] = __floats2bfloat162_rn(a3.x, a3.y);
        r[7] = __floats2bfloat162_rn(a3.z, a3.w);
        *(uint4*)(g_encb + base)     = *(uint4*)&r[0];
        *(uint4*)(g_encb + base + 8) = *(uint4*)&r[4];
    } else if (blockIdx.x < 8704) {
        size_t gid = (size_t)(blockIdx.x - 8192) * 256 + threadIdx.x;
        size_t base = gid * 8;
        size_t i = base >> 10, k = base & 1023;
        const float* src = attn_w + i * H3 + 2 * HDIM + k;
        float4 a = *(const float4*)src;
        float4 b = *(const float4*)(src + 4);
        __nv_bfloat162 r[4];
        r[0] = __floats2bfloat162_rn(a.x, a.y);
        r[1] = __floats2bfloat162_rn(a.z, a.w);
        r[2] = __floats2bfloat162_rn(b.x, b.y);
        r[3] = __floats2bfloat162_rn(b.z, b.w);
        *(uint4*)(g_wb + base) = *(uint4*)r;
    } else {
        int warp = ((blockIdx.x - 8704) * 256 + threadIdx.x) >> 5;  // 0..1023
        int lane = threadIdx.x & 31;
        const float* wrow = attn_w + (size_t)warp * H3;
        float s = 0.f;
        #pragma unroll 8
        for (int j = lane; j < 2 * HDIM; j += 32)
            s += hidden[j] * wrow[j];
        #pragma unroll
        for (int off = 16; off; off >>= 1)
            s += __shfl_down_sync(0xffffffffu, s, off);
        if (lane == 0) g_c[warp] = s + attn_b[warp];
    }
}

// ---------------------------------------------------------------------------
// Kernel 2: persistent bf16 m16n8k16 GEMM over 2048 (tile, pass) units.
//   4 warps = 2(M) x 2(N).  Warp tile 64x64 (mt=4, nt=8).  acc = 128 regs.
//   (R14/R16 proven version — unchanged.)
// ---------------------------------------------------------------------------
__global__ __launch_bounds__(NTHR, 2)
void attn_main_kernel(const float* __restrict__ v_w) {
    extern __shared__ char smem[];
    const unsigned sb = smem_u32(smem);
    const int tid  = threadIdx.x;
    const int wid  = tid >> 5;
    const int lane = tid & 31;
    const int g    = lane >> 2;        // 0..7
    const int c    = lane & 3;         // 0..3
    const int m0   = (wid & 1) * 64;   // 2 M-warps
    const int n0   = (wid >> 1) * 64;  // 2 N-warps

    float* red = (float*)(smem + SM_RED);

    const int arow  = m0 + ((lane >> 3) & 1) * 8 + (lane & 7); // + mt*16
    const int aswz  = arow & 7;
    const int acol  = lane >> 4;                               // 0..1 (k half)
    const int brow  = n0 + (lane >> 4) * 8 + (lane & 7);       // + p*16
    const int bswz  = brow & 7;
    const int bcol  = (lane >> 3) & 1;                         // 0..1 (k half)

    for (int u = blockIdx.x; u < NUNITS; u += GRID_MAIN) {
        const int tile = u >> 3;
        const int pass = u & 7;
        const int s0   = tile * BM;
        const int i0   = pass * BN;

        load_chunk(sb, 0, 0, s0, i0, tid);
        load_chunk(sb, 1, 1, s0, i0, tid);

        float acc[4][8][4];
        #pragma unroll
        for (int mt = 0; mt < 4; mt++)
            #pragma unroll
            for (int nt = 0; nt < 8; nt++)
                #pragma unroll
                for (int q = 0; q < 4; q++) acc[mt][nt][q] = 0.f;

        for (int ch = 0; ch < CH_PER_UNIT; ch++) {
            const int stage = ch % NSTAGE;
            if (ch < CH_PER_UNIT - 1)
                asm volatile("cp.async.wait_group 1;" ::: "memory");
            else
                asm volatile("cp.async.wait_group 0;" ::: "memory");
            __syncthreads();

            if (ch + 2 < CH_PER_UNIT)
                load_chunk(sb, (ch + 2) % NSTAGE, ch + 2, s0, i0, tid);

            const unsigned aS = sb + SM_A + stage * STG;
            const unsigned bS = sb + SM_B + stage * STG;

            #pragma unroll
            for (int ks = 0; ks < 4; ks++) {   // four k16 steps cover KCH=64
                uint32_t af[4][4], bf[4][4];
                const int aq = ((ks * 2 + acol) ^ aswz) * 16;
                const int bq = ((ks * 2 + bcol) ^ bswz) * 16;
                #pragma unroll
                for (int mt = 0; mt < 4; mt++)
                    ldsm4(af[mt], aS + (unsigned)((arow + mt * 16) * 128 + aq));
                #pragma unroll
                for (int p = 0; p < 4; p++)
                    ldsm4(bf[p], bS + (unsigned)((brow + p * 16) * 128 + bq));
                #pragma unroll
                for (int p = 0; p < 4; p++) {
                    #pragma unroll
                    for (int mt = 0; mt < 4; mt++) {
                        mma16(acc[mt][2 * p + 0], af[mt], bf[p][0], bf[p][1]);
                        mma16(acc[mt][2 * p + 1], af[mt], bf[p][2], bf[p][3]);
                    }
                }
            }
        }

        // unit epilogue: tanh + v-dot -> per-thread partials
        float part[8];
        #pragma unroll
        for (int r = 0; r < 8; r++) part[r] = 0.f;
        #pragma unroll
        for (int mt = 0; mt < 4; mt++) {
            #pragma unroll
            for (int nt = 0; nt < 8; nt++) {
                int i = i0 + n0 + nt * 8 + c * 2;
                float2 cv = __ldg((const float2*)(g_c + i));
                float2 vv = __ldg((const float2*)(v_w + i));
                part[mt*2+0] = fmaf(vv.x, fast_tanh(acc[mt][nt][0] + cv.x),
                               fmaf(vv.y, fast_tanh(acc[mt][nt][1] + cv.y),
                                    part[mt*2+0]));
                part[mt*2+1] = fmaf(vv.x, fast_tanh(acc[mt][nt][2] + cv.x),
                               fmaf(vv.y, fast_tanh(acc[mt][nt][3] + cv.y),
                                    part[mt*2+1]));
            }
        }
        #pragma unroll
        for (int r = 0; r < 8; r++) {
            part[r] += __shfl_xor_sync(0xffffffffu, part[r], 1);
            part[r] += __shfl_xor_sync(0xffffffffu, part[r], 2);
        }
        if (c == 0) {
            const int nw = wid >> 1;
            #pragma unroll
            for (int mt = 0; mt < 4; mt++) {
                #pragma unroll
                for (int h = 0; h < 2; h++) {
                    int row = m0 + mt * 16 + h * 8 + g;
                    red[nw * 128 + row] = part[mt * 2 + h];
                }
            }
        }
        __syncthreads();                       // also fences stage reuse
        g_lp[pass * S_LEN + s0 + tid] = red[tid] + red[128 + tid];
    }
}

// ---------------------------------------------------------------------------
// Kernel 3 (fused tail): exp + block sums + co-resident spin barrier +
// redundant deterministic total + normalize. 128 blocks, all resident.
// Ticket counter is monotone (never reset) -> safe under graph replay.
// ---------------------------------------------------------------------------
__global__ void tail_kernel(float* __restrict__ out) {
    __shared__ float sr[8];
    __shared__ unsigned long long base_s;
    const int t = threadIdx.x;
    const int s = blockIdx.x * 256 + t;

    float logit = 0.f;
    #pragma unroll
    for (int p = 0; p < NPASS; p++)
        logit += g_lp[p * S_LEN + s];
    float ex = expf(logit);                    // |logit| <= ~26, unshifted safe
    out[s] = ex;

    float w = ex;
    #pragma unroll
    for (int off = 16; off; off >>= 1)
        w += __shfl_down_sync(0xffffffffu, w, off);
    if ((t & 31) == 0) sr[t >> 5] = w;
    __syncthreads();

    if (t == 0) {
        float bs = 0.f;
        #pragma unroll
        for (int y = 0; y < 8; y++) bs += sr[y];
        g_part[blockIdx.x] = bs;
        __threadfence();
        unsigned long long tk = atomicAdd(&g_tick, 1ull);
        base_s = (tk / NBLK_TAIL) * NBLK_TAIL;  // this launch's round base
    }
    __syncthreads();
    if (t == 0) {
        // spin until all 128 blocks of this round have arrived
        while (*((volatile unsigned long long*)&g_tick) < base_s + NBLK_TAIL) {}
    }
    __syncthreads();

    // redundant deterministic total (fixed order, same in every block)
    float tot = 0.f;
    #pragma unroll
    for (int b = 0; b < NBLK_TAIL; b++) tot += g_part[b];
    out[s] = ex * (1.f / tot);
}

// ---------------------------------------------------------------------------
extern "C" void kernel_launch(void* const* d_in, const int* in_sizes, int n_in,
                              void* d_out, int out_size) {
    const float* hidden = (const float*)d_in[0];
    const float* enc    = (const float*)d_in[1];
    const float* attn_w = (const float*)d_in[2];
    const float* attn_b = (const float*)d_in[3];
    const float* v_w    = (const float*)d_in[4];
    float* out = (float*)d_out;

    cudaFuncSetAttribute(attn_main_kernel,
                         cudaFuncAttributeMaxDynamicSharedMemorySize, SMEM_TOTAL);

    prep_all_kernel<<<8832, 256>>>(enc, attn_w, hidden, attn_b);
    attn_main_kernel<<<GRID_MAIN, NTHR, SMEM_TOTAL>>>(v_w);
    tail_kernel<<<NBLK_TAIL, 256>>>(out);
}